// round 15
// baseline (speedup 1.0000x reference)
#include <cuda_runtime.h>
#include <math.h>
#include <stdint.h>

#define B 32
#define T 128
#define E 512
#define H 1024
#define V 32000
#define L 64
#define BOS 1
#define NB 512
#define R4H 4096
#define LCTAS 500         // logits CTAs, 64 vocab rows each
#define PREP_BLOCKS 61184

// ---------------- static device scratch ----------------
__device__ float g_xsT[T * E * B];
__device__ float g_xdT[E * B];
__device__ float g_h0T[2][H * B];
__device__ float g_h1T[2][H * B];
__device__ float g_c0T[H * B];
__device__ float g_c1T[H * B];
__device__ float g_part0[16 * R4H * B];
__device__ float g_part1[16 * R4H * B];
__device__ float g_pval[LCTAS * B];
__device__ int   g_pidx[LCTAS * B];
__device__ unsigned g_bar_count;

// transposed weights WT[k][row]; outWT padded +8 k-rows for branch-free prefetch
__device__ float g_WTe0[(E + H + 2) * R4H];
__device__ float g_WTe1[(H + H + 2) * R4H];
__device__ float g_WTd0[(E + H + 2) * R4H];
__device__ float g_WTd1[(H + H + 2) * R4H];
__device__ float g_outWT[(H + 8) * V];

__device__ __forceinline__ float sigm(float x) { return 1.0f / (1.0f + expf(-x)); }

#define FMA2(acc, a, b) asm("fma.rn.f32x2 %0, %1, %2, %0;" : "+l"(acc) : "l"(a), "l"(b))
#define ADD2(d, a, b) asm("add.rn.f32x2 %0, %1, %2;" : "=l"(d) : "l"(a), "l"(b))
#define UNPACK2(lo, hi, v) asm("mov.b64 {%0,%1}, %2;" : "=f"(lo), "=f"(hi) : "l"(v))

#define CP_ASYNC16(dst, src) \
    asm volatile("cp.async.cg.shared.global [%0], [%1], 16;" :: "r"(dst), "l"(src))
#define CP_COMMIT() asm volatile("cp.async.commit_group;")
#define CP_WAIT1()  asm volatile("cp.async.wait_group 1;")
#define CP_WAIT0()  asm volatile("cp.async.wait_group 0;")

// 8 packed FMAs, no operand-duplication MOVs: w2 = 4 weight rows (2 f32x2 pairs),
// xa/xb = 4 pre-duplicated x values from smem.
#define MAC_K(A, w2, xa, xb) do {                                   \
    FMA2(A[0][0], (w2).x, (xa).x); FMA2(A[1][0], (w2).y, (xa).x);   \
    FMA2(A[0][1], (w2).x, (xa).y); FMA2(A[1][1], (w2).y, (xa).y);   \
    FMA2(A[0][2], (w2).x, (xb).x); FMA2(A[1][2], (w2).y, (xb).x);   \
    FMA2(A[0][3], (w2).x, (xb).y); FMA2(A[1][3], (w2).y, (xb).y);   \
} while (0)

// ---------------- grid barrier: RED arrive + paced acquire poll ----------------
__device__ __forceinline__ void grid_barrier(unsigned target)
{
    __syncthreads();
    if (threadIdx.x == 0) {
        __threadfence();
        atomicAdd(&g_bar_count, 1u);
        while (true) {
            unsigned v;
            asm volatile("ld.acquire.gpu.u32 %0, [%1];"
                         : "=r"(v) : "l"(&g_bar_count) : "memory");
            if (v >= target) break;
            __nanosleep(128);
        }
    }
    __syncthreads();
}

// ---------------- prep: transposes + encoder gather + counter reset ----------------
__device__ void do_tr(const float* __restrict__ in, float* __restrict__ out,
                      int C, int OS, int koff, int bx, int by)
{
    __shared__ float t[32][33];
    const int tx = threadIdx.x & 31, ty = threadIdx.x >> 5;
    const int r0 = by * 32, c0 = bx * 32;
    #pragma unroll
    for (int i = 0; i < 4; i++)
        t[ty + 8 * i][tx] = in[(size_t)(r0 + ty + 8 * i) * C + (c0 + tx)];
    __syncthreads();
    #pragma unroll
    for (int i = 0; i < 4; i++)
        out[(size_t)(c0 + koff + ty + 8 * i) * OS + (r0 + tx)] = t[tx][ty + 8 * i];
}

__device__ void do_gather(const float* __restrict__ emb,
                          const int* __restrict__ tokens, int bx, int t)
{
    __shared__ float tile[B][132];
    const int k0 = bx * 128;
    const int w = threadIdx.x >> 5, lane = threadIdx.x & 31;
    #pragma unroll
    for (int r = 0; r < 4; r++) {
        int b = w * 4 + r;
        int tokb = tokens[b * T + t];
        float4 v = *(const float4*)(emb + (size_t)tokb * E + k0 + lane * 4);
        tile[b][lane * 4 + 0] = v.x; tile[b][lane * 4 + 1] = v.y;
        tile[b][lane * 4 + 2] = v.z; tile[b][lane * 4 + 3] = v.w;
    }
    __syncthreads();
    float* out = g_xsT + (size_t)t * E * B + (size_t)k0 * B;
    #pragma unroll
    for (int i = 0; i < 4; i++) {
        int idx = threadIdx.x + i * 256;
        int k = idx >> 3, b4 = (idx & 7) * 4;
        *(float4*)(out + k * B + b4) = make_float4(tile[b4+0][k], tile[b4+1][k],
                                                   tile[b4+2][k], tile[b4+3][k]);
    }
}

__global__ __launch_bounds__(256) void prep_kernel(
    const float* __restrict__ eWih0, const float* __restrict__ eWhh0,
    const float* __restrict__ eWih1, const float* __restrict__ eWhh1,
    const float* __restrict__ dWih0, const float* __restrict__ dWhh0,
    const float* __restrict__ dWih1, const float* __restrict__ dWhh1,
    const float* __restrict__ outW,  const float* __restrict__ emb,
    const int*   __restrict__ src)
{
    if (blockIdx.x == 0 && threadIdx.x == 0) g_bar_count = 0u;
    int i = blockIdx.x;
    if (i < 2048)  { do_tr(eWih0, g_WTe0, E, R4H, 0, i & 15, i >> 4); return; }
    i -= 2048;
    if (i < 4096)  { do_tr(eWhh0, g_WTe0, H, R4H, E, i & 31, i >> 5); return; }
    i -= 4096;
    if (i < 4096)  { do_tr(eWih1, g_WTe1, H, R4H, 0, i & 31, i >> 5); return; }
    i -= 4096;
    if (i < 4096)  { do_tr(eWhh1, g_WTe1, H, R4H, H, i & 31, i >> 5); return; }
    i -= 4096;
    if (i < 2048)  { do_tr(dWih0, g_WTd0, E, R4H, 0, i & 15, i >> 4); return; }
    i -= 2048;
    if (i < 4096)  { do_tr(dWhh0, g_WTd0, H, R4H, E, i & 31, i >> 5); return; }
    i -= 4096;
    if (i < 4096)  { do_tr(dWih1, g_WTd1, H, R4H, 0, i & 31, i >> 5); return; }
    i -= 4096;
    if (i < 4096)  { do_tr(dWhh1, g_WTd1, H, R4H, H, i & 31, i >> 5); return; }
    i -= 4096;
    if (i < 32000) { do_tr(outW,  g_outWT, H, V,  0, i & 31, i >> 5); return; }
    i -= 32000;
    do_gather(emb, src, i & 3, i >> 2);
}

// ---------------- gates: cp.async weights + dup-x staging, 32 rows x 16 batches -----
__device__ __forceinline__ void fill_w(uint32_t s_w_u32, int buf,
                                       const float* __restrict__ wsrc)
{
    const int tid = threadIdx.x;
    #pragma unroll
    for (int r = 0; r < 2; r++) {
        int seg = tid + r * 256;          // 512 segs of 16B = 16 k-rows x 512B
        int kk = seg >> 5, sof = seg & 31;
        const float* src = wsrc + (size_t)kk * R4H + sof * 4;
        CP_ASYNC16(s_w_u32 + buf * 8192 + seg * 16, src);
    }
    CP_COMMIT();
}

__device__ void gates_phase(int taskbase, int nslice, int KS,
                            const float* __restrict__ xT, int KX,
                            const float* __restrict__ hT,
                            const float* __restrict__ WT,
                            float* __restrict__ part,
                            float* __restrict__ s_xd,   // 8 KB: 2 x 1024 floats
                            float* __restrict__ s_w)    // 16 KB: 2 x 2048 floats
{
    const int tid = threadIdx.x;
    const int gw = blockIdx.x * 8 + (tid >> 5);
    const int task = gw - taskbase;
    if (task < 0 || task >= nslice * 256) return;   // CTA-uniform
    const int lane = tid & 31;
    const int s = task >> 8;
    const int pos = task & 255;
    const int bh = pos & 1, rg = pos >> 1;
    const int myrow = rg * 32 + (lane >> 2) * 4;
    const int bcol  = bh * 16 + (lane & 3) * 4;
    const int klo = s * KS;
    const int rowBase = (pos >> 3) * 128;           // same for all 8 warps
    const int wlr = myrow - rowBase;                // 0..124
    const uint32_t s_w_u32 = (uint32_t)__cvta_generic_to_shared(s_w);

    // dup-staging thread mapping: chunk-local k = tid>>4, batches (tid&15)*2..+1
    const int dk = tid >> 4;
    const int db = (tid & 15) * 2;

    unsigned long long acc[2][4];
    #pragma unroll
    for (int a = 0; a < 2; a++)
        #pragma unroll
        for (int b = 0; b < 4; b++) acc[a][b] = 0ull;

    const float* wsrc0 = WT + (size_t)klo * R4H + rowBase;
    const int nch = KS >> 4;                        // 16-k chunks
    fill_w(s_w_u32, 0, wsrc0);
    // dup chunk 0 directly from gmem (x is L2-hot; boundary 16-aligned)
    {
        int gk = klo + dk;
        const float* src = (gk < KX) ? xT + (size_t)gk * B + db
                                     : hT + (size_t)(gk - KX) * B + db;
        float2 v = *(const float2*)src;
        *(float4*)(s_xd + tid * 4) = make_float4(v.x, v.x, v.y, v.y);
    }
    int buf = 0, dbuf = 0;

    for (int cc = 0; cc < nch; cc++) {
        float2 vn = make_float2(0.f, 0.f);
        if (cc + 1 < nch) {
            fill_w(s_w_u32, buf ^ 1, wsrc0 + (size_t)(cc + 1) * 16 * R4H);
            int gk = klo + (cc + 1) * 16 + dk;      // issue LDG before the waits
            const float* src = (gk < KX) ? xT + (size_t)gk * B + db
                                         : hT + (size_t)(gk - KX) * B + db;
            vn = *(const float2*)src;
            CP_WAIT1();
        } else {
            CP_WAIT0();
        }
        __syncthreads();                            // w(cc) + dup(cc) visible

        if (cc + 1 < nch)
            *(float4*)(s_xd + ((dbuf ^ 1) << 10) + tid * 4) =
                make_float4(vn.x, vn.x, vn.y, vn.y);

        const float* ws = s_w + (buf << 11) + wlr;
        const float* xd = s_xd + (dbuf << 10) + bcol * 2;
        #pragma unroll
        for (int kk = 0; kk < 16; kk++) {
            ulonglong2 w2 = *(const ulonglong2*)(ws + kk * 128);
            ulonglong2 xa = *(const ulonglong2*)(xd + kk * 64);
            ulonglong2 xb = *(const ulonglong2*)(xd + kk * 64 + 4);
            MAC_K(acc, w2, xa, xb);
        }
        __syncthreads();                            // reads done before refills
        buf ^= 1; dbuf ^= 1;
    }

    float vr[4][4];
    #pragma unroll
    for (int b = 0; b < 4; b++) {
        UNPACK2(vr[0][b], vr[1][b], acc[0][b]);
        UNPACK2(vr[2][b], vr[3][b], acc[1][b]);
    }
    float* p = part + (size_t)s * R4H * B;
    #pragma unroll
    for (int r = 0; r < 4; r++)
        *(float4*)(p + (size_t)(myrow + r) * B + bcol) =
            make_float4(vr[r][0], vr[r][1], vr[r][2], vr[r][3]);
}

// ---------------- cell: combine partials + bias + LSTM cell ----------------
__device__ void cell_phase(int blockbase, int nslice,
                           const float* __restrict__ part,
                           const float* __restrict__ bias,
                           float* __restrict__ cT, float* __restrict__ hOut)
{
    const int cb = blockIdx.x - blockbase;
    if (cb < 0 || cb >= 128) return;
    const int idx = cb * 256 + threadIdx.x;
    const int j = idx >> 5, b = idx & 31;
    float g[4];
    #pragma unroll
    for (int gg = 0; gg < 4; gg++) g[gg] = bias[gg * H + j];
    #pragma unroll 4
    for (int s = 0; s < nslice; s++) {
        const float* p = part + (size_t)s * R4H * B + b;
        #pragma unroll
        for (int gg = 0; gg < 4; gg++)
            g[gg] += p[(size_t)(gg * H + j) * B];
    }
    float c_old = cT[j * B + b];
    float c_new = sigm(g[1]) * c_old + sigm(g[0]) * tanhf(g[2]);
    cT[j * B + b]   = c_new;
    hOut[j * B + b] = sigm(g[3]) * tanhf(c_new);
}

// ---------------- logits: dup-x staged 64k chunks, branch-free w prefetch -----------
__device__ void logits_phase(const float* __restrict__ h1T,
                             const float* __restrict__ outB,
                             float* __restrict__ out, int step,
                             float* __restrict__ s_x,
                             unsigned long long* __restrict__ s_aux)
{
    unsigned long long (*s_comb)[32][8] =
        (unsigned long long (*)[32][8])s_aux;                  // 8 KB
    float* s_av = (float*)(s_aux + 1024);                      // [2][32]
    int*   s_ai = (int*)((float*)(s_aux + 1024) + 64);         // [2][32]

    const int c = blockIdx.x;
    if (c >= LCTAS) return;
    const int tid = threadIdx.x;
    const int w = tid >> 5, lane = tid & 31;
    const int ks = w & 1, bh = (w >> 1) & 1, rgh = w >> 2;
    const int vrow = c * 64 + rgh * 32 + (lane >> 2) * 4;
    const int bcol = bh * 16 + (lane & 3) * 4;

    unsigned long long acc[2][4];
    #pragma unroll
    for (int a = 0; a < 2; a++)
        #pragma unroll
        for (int b = 0; b < 4; b++) acc[a][b] = 0ull;

    // continuous 4-deep weight prefetch over this ks-half (pad rows absorb tail)
    const float* wp0 = g_outWT + (size_t)(ks * 512) * V + vrow;
    ulonglong2 wbuf[4];
    #pragma unroll
    for (int i = 0; i < 4; i++)
        wbuf[i] = *(const ulonglong2*)(wp0 + (size_t)i * V);
    const float* wnext = wp0 + (size_t)4 * V;

    for (int ci = 0; ci < 8; ci++) {
        __syncthreads();                  // prior chunk reads done
        #pragma unroll
        for (int r = 0; r < 4; r++) {
            int i = tid + r * 256;        // 0..1023
            int kl = i >> 4, b = (i & 15) * 2;
            float2 vA = *(const float2*)(h1T + (size_t)(ci * 64 + kl) * B + b);
            float2 vB = *(const float2*)(h1T + (size_t)(512 + ci * 64 + kl) * B + b);
            *(float4*)(s_x + i * 4)        = make_float4(vA.x, vA.x, vA.y, vA.y);
            *(float4*)(s_x + 4096 + i * 4) = make_float4(vB.x, vB.x, vB.y, vB.y);
        }
        __syncthreads();

        const float* xd = s_x + ks * 4096 + bcol * 2;
        #pragma unroll 1
        for (int kk = 0; kk < 64; kk += 4) {
            #pragma unroll
            for (int u = 0; u < 4; u++) {
                ulonglong2 w2 = wbuf[u];
                wbuf[u] = *(const ulonglong2*)wnext;
                wnext += V;
                ulonglong2 xa = *(const ulonglong2*)(xd + (kk + u) * 64);
                ulonglong2 xb = *(const ulonglong2*)(xd + (kk + u) * 64 + 4);
                MAC_K(acc, w2, xa, xb);
            }
        }
    }
    __syncthreads();

    if (ks) {
        #pragma unroll
        for (int a = 0; a < 8; a++) s_comb[w >> 1][lane][a] = acc[a >> 2][a & 3];
    }
    __syncthreads();
    if (!ks) {
        #pragma unroll
        for (int a = 0; a < 8; a++) {
            unsigned long long o = s_comb[w >> 1][lane][a];
            ADD2(acc[a >> 2][a & 3], acc[a >> 2][a & 3], o);
        }
        float4 b4 = *(const float4*)(outB + vrow);
        float vr[4][4];
        #pragma unroll
        for (int b = 0; b < 4; b++) {
            UNPACK2(vr[0][b], vr[1][b], acc[0][b]);
            UNPACK2(vr[2][b], vr[3][b], acc[1][b]);
            vr[0][b] += b4.x; vr[1][b] += b4.y; vr[2][b] += b4.z; vr[3][b] += b4.w;
        }
        float mval[4]; int midx[4];
        #pragma unroll
        for (int b = 0; b < 4; b++) {
            *(float4*)(out + (size_t)(bcol + b) * (L * V) + (size_t)step * V + vrow) =
                make_float4(vr[0][b], vr[1][b], vr[2][b], vr[3][b]);
            float bv = vr[0][b]; int bi = vrow;
            #pragma unroll
            for (int r = 1; r < 4; r++)
                if (vr[r][b] > bv) { bv = vr[r][b]; bi = vrow + r; }
            mval[b] = bv; midx[b] = bi;
        }
        #pragma unroll
        for (int off = 16; off >= 4; off >>= 1) {
            #pragma unroll
            for (int b = 0; b < 4; b++) {
                float ov = __shfl_down_sync(0xffffffffu, mval[b], off);
                int   oi = __shfl_down_sync(0xffffffffu, midx[b], off);
                if (ov > mval[b] || (ov == mval[b] && oi < midx[b])) {
                    mval[b] = ov; midx[b] = oi;
                }
            }
        }
        if (lane < 4) {
            #pragma unroll
            for (int b = 0; b < 4; b++) {
                s_av[rgh * 32 + bh * 16 + lane * 4 + b] = mval[b];
                s_ai[rgh * 32 + bh * 16 + lane * 4 + b] = midx[b];
            }
        }
    }
    __syncthreads();
    if (tid < 32) {
        float v0 = s_av[tid], v1 = s_av[32 + tid];
        int   i0 = s_ai[tid], i1 = s_ai[32 + tid];
        bool take1 = (v1 > v0) || (v1 == v0 && i1 < i0);
        g_pval[c * B + tid] = take1 ? v1 : v0;
        g_pidx[c * B + tid] = take1 ? i1 : i0;
    }
}

// ---------------- argmax final + next-token embedding gather ----------------
__device__ void argmax_gather_phase(const float* __restrict__ emb, bool do_argmax,
                                    unsigned long long* __restrict__ s_aux)
{
    float* sval = (float*)s_aux;             // 256 floats
    int*   sidx = (int*)(s_aux + 128);       // 256 ints
    const int c = blockIdx.x;
    if (c >= B) return;
    const int b = c, tid = threadIdx.x;
    int tk;
    if (do_argmax) {
        float bv = -INFINITY; int bi = 0x7fffffff;
        for (int i2 = tid; i2 < LCTAS; i2 += 256) {
            float v = g_pval[i2 * B + b]; int i = g_pidx[i2 * B + b];
            if (v > bv || (v == bv && i < bi)) { bv = v; bi = i; }
        }
        sval[tid] = bv; sidx[tid] = bi;
        __syncthreads();
        for (int off = 128; off; off >>= 1) {
            if (tid < off) {
                float v = sval[tid + off]; int i = sidx[tid + off];
                if (v > sval[tid] || (v == sval[tid] && i < sidx[tid])) {
                    sval[tid] = v; sidx[tid] = i;
                }
            }
            __syncthreads();
        }
        tk = sidx[0];
    } else {
        tk = BOS;
    }
    for (int k = tid; k < E; k += 256)
        g_xdT[k * B + b] = emb[(size_t)tk * E + k];
}

// ---------------- persistent model kernel ----------------
__global__ __launch_bounds__(256, 4) void model_kernel(
    const float* __restrict__ emb,
    const float* __restrict__ eb0, const float* __restrict__ eb1,
    const float* __restrict__ db0, const float* __restrict__ db1,
    const float* __restrict__ outB,
    float* __restrict__ out)
{
    __shared__ float s_x[8192];                 // 32 KB: logits dup-x / gates s_xd
    __shared__ unsigned long long s_aux[2048];  // 16 KB: w dbl-buf / comb / argmax

    const int tid = threadIdx.x;
    unsigned bt = 0;

    for (int i = blockIdx.x * 256 + tid; i < H * B; i += NB * 256) {
        g_h0T[0][i] = 0.f; g_h1T[0][i] = 0.f;
        g_c0T[i] = 0.f;    g_c1T[i] = 0.f;
    }
    grid_barrier(bt += NB);

    int p0 = 0, p1 = 0;
    float* s_w  = (float*)s_aux;
    float* s_xd = s_x;                          // gates dup buffers (8 KB)

    // ---- encoder, software-pipelined (L1(t) || L0(t+1)) ----
    gates_phase(0, 6, 256, g_xsT, E, g_h0T[p0], g_WTe0, g_part0, s_xd, s_w); // L0 t=0
    grid_barrier(bt += NB);
    cell_phase(0, 6, g_part0, eb0, g_c0T, g_h0T[p0 ^ 1]);
    p0 ^= 1;
    grid_barrier(bt += NB);

    for (int t = 0; t < T; t++) {
        gates_phase(0, 8, 256, g_h0T[p0], H, g_h1T[p1], g_WTe1, g_part1,
                    s_xd, s_w);                                              // L1(t)
        if (t + 1 < T)
            gates_phase(2048, 6, 256, g_xsT + (size_t)(t + 1) * E * B, E,
                        g_h0T[p0], g_WTe0, g_part0, s_xd, s_w);              // L0(t+1)
        grid_barrier(bt += NB);
        cell_phase(0, 8, g_part1, eb1, g_c1T, g_h1T[p1 ^ 1]);
        p1 ^= 1;
        if (t + 1 < T) {
            cell_phase(128, 6, g_part0, eb0, g_c0T, g_h0T[p0 ^ 1]);
            p0 ^= 1;
        }
        grid_barrier(bt += NB);
    }

    // ---- BOS gather ----
    argmax_gather_phase(emb, false, s_aux);
    grid_barrier(bt += NB);

    // ---- greedy decoder ----
    for (int s = 0; s < L; s++) {
        gates_phase(0, 16, 96, g_xdT, E, g_h0T[p0], g_WTd0, g_part0, s_xd, s_w);
        grid_barrier(bt += NB);
        cell_phase(0, 16, g_part0, db0, g_c0T, g_h0T[p0 ^ 1]);
        p0 ^= 1;
        grid_barrier(bt += NB);
        gates_phase(0, 16, 128, g_h0T[p0], H, g_h1T[p1], g_WTd1, g_part1, s_xd, s_w);
        grid_barrier(bt += NB);
        cell_phase(0, 16, g_part1, db1, g_c1T, g_h1T[p1 ^ 1]);
        p1 ^= 1;
        grid_barrier(bt += NB);
        logits_phase(g_h1T[p1], outB, out, s, s_x, s_aux);
        grid_barrier(bt += NB);
        argmax_gather_phase(emb, true, s_aux);
        grid_barrier(bt += NB);
    }
}

// ---------------- host orchestration: 2 launches per call ----------------
extern "C" void kernel_launch(void* const* d_in, const int* in_sizes, int n_in,
                              void* d_out, int out_size)
{
    const int*   src   = (const int*)  d_in[0];
    const float* emb   = (const float*)d_in[1];
    const float* eWih0 = (const float*)d_in[2];
    const float* eWhh0 = (const float*)d_in[3];
    const float* eb0   = (const float*)d_in[4];
    const float* eWih1 = (const float*)d_in[5];
    const float* eWhh1 = (const float*)d_in[6];
    const float* eb1   = (const float*)d_in[7];
    const float* dWih0 = (const float*)d_in[8];
    const float* dWhh0 = (const float*)d_in[9];
    const float* db0   = (const float*)d_in[10];
    const float* dWih1 = (const float*)d_in[11];
    const float* dWhh1 = (const float*)d_in[12];
    const float* db1   = (const float*)d_in[13];
    const float* outW  = (const float*)d_in[14];
    const float* outB  = (const float*)d_in[15];
    float* out = (float*)d_out;

    prep_kernel<<<PREP_BLOCKS, 256>>>(eWih0, eWhh0, eWih1, eWhh1,
                                      dWih0, dWhh0, dWih1, dWhh1,
                                      outW, emb, src);

    model_kernel<<<NB, 256>>>(emb, eb0, eb1, db0, db1, outB, out);
}

// round 16
// speedup vs baseline: 1.5509x; 1.5509x over previous
#include <cuda_runtime.h>
#include <math.h>
#include <stdint.h>

#define B 32
#define T 128
#define E 512
#define H 1024
#define V 32000
#define L 64
#define BOS 1
#define NB 512
#define R4H 4096
#define LCTAS 500         // logits CTAs, 64 vocab rows each
#define PREP_BLOCKS 61184

// ---------------- static device scratch ----------------
__device__ float g_xsT[T * E * B];
__device__ float g_xdT[E * B];
__device__ float g_h0T[2][H * B];
__device__ float g_h1T[2][H * B];
__device__ float g_c0T[H * B];
__device__ float g_c1T[H * B];
__device__ float g_part0[16 * R4H * B];
__device__ float g_part1[16 * R4H * B];
__device__ float g_pval[LCTAS * B];
__device__ int   g_pidx[LCTAS * B];
__device__ unsigned g_bar_count;

// transposed weights WT[k][row]
__device__ float g_WTe0[(E + H + 2) * R4H];
__device__ float g_WTe1[(H + H + 2) * R4H];
__device__ float g_WTd0[(E + H + 2) * R4H];
__device__ float g_WTd1[(H + H + 2) * R4H];
__device__ float g_outWT[(H + 2) * V];

__device__ __forceinline__ float sigm(float x) { return 1.0f / (1.0f + expf(-x)); }

#define PACKXX(d, f)  asm("mov.b64 %0, {%1,%1};" : "=l"(d) : "f"(f))
#define FMA2(acc, a, b) asm("fma.rn.f32x2 %0, %1, %2, %0;" : "+l"(acc) : "l"(a), "l"(b))
#define ADD2(d, a, b) asm("add.rn.f32x2 %0, %1, %2;" : "=l"(d) : "l"(a), "l"(b))
#define UNPACK2(lo, hi, v) asm("mov.b64 {%0,%1}, %2;" : "=f"(lo), "=f"(hi) : "l"(v))

#define CP_ASYNC16(dst, src) \
    asm volatile("cp.async.cg.shared.global [%0], [%1], 16;" :: "r"(dst), "l"(src))
#define CP_COMMIT() asm volatile("cp.async.commit_group;")
#define CP_WAIT1()  asm volatile("cp.async.wait_group 1;")
#define CP_WAIT0()  asm volatile("cp.async.wait_group 0;")

// ---------------- grid barrier: RED arrive + paced acquire poll ----------------
__device__ __forceinline__ void grid_barrier(unsigned target)
{
    __syncthreads();
    if (threadIdx.x == 0) {
        __threadfence();
        atomicAdd(&g_bar_count, 1u);
        while (true) {
            unsigned v;
            asm volatile("ld.acquire.gpu.u32 %0, [%1];"
                         : "=r"(v) : "l"(&g_bar_count) : "memory");
            if (v >= target) break;
            __nanosleep(128);
        }
    }
    __syncthreads();
}

// ---------------- prep: transposes + encoder gather + counter reset ----------------
__device__ void do_tr(const float* __restrict__ in, float* __restrict__ out,
                      int C, int OS, int koff, int bx, int by)
{
    __shared__ float t[32][33];
    const int tx = threadIdx.x & 31, ty = threadIdx.x >> 5;
    const int r0 = by * 32, c0 = bx * 32;
    #pragma unroll
    for (int i = 0; i < 4; i++)
        t[ty + 8 * i][tx] = in[(size_t)(r0 + ty + 8 * i) * C + (c0 + tx)];
    __syncthreads();
    #pragma unroll
    for (int i = 0; i < 4; i++)
        out[(size_t)(c0 + koff + ty + 8 * i) * OS + (r0 + tx)] = t[tx][ty + 8 * i];
}

__device__ void do_gather(const float* __restrict__ emb,
                          const int* __restrict__ tokens, int bx, int t)
{
    __shared__ float tile[B][132];
    const int k0 = bx * 128;
    const int w = threadIdx.x >> 5, lane = threadIdx.x & 31;
    #pragma unroll
    for (int r = 0; r < 4; r++) {
        int b = w * 4 + r;
        int tokb = tokens[b * T + t];
        float4 v = *(const float4*)(emb + (size_t)tokb * E + k0 + lane * 4);
        tile[b][lane * 4 + 0] = v.x; tile[b][lane * 4 + 1] = v.y;
        tile[b][lane * 4 + 2] = v.z; tile[b][lane * 4 + 3] = v.w;
    }
    __syncthreads();
    float* out = g_xsT + (size_t)t * E * B + (size_t)k0 * B;
    #pragma unroll
    for (int i = 0; i < 4; i++) {
        int idx = threadIdx.x + i * 256;
        int k = idx >> 3, b4 = (idx & 7) * 4;
        *(float4*)(out + k * B + b4) = make_float4(tile[b4+0][k], tile[b4+1][k],
                                                   tile[b4+2][k], tile[b4+3][k]);
    }
}

__global__ __launch_bounds__(256) void prep_kernel(
    const float* __restrict__ eWih0, const float* __restrict__ eWhh0,
    const float* __restrict__ eWih1, const float* __restrict__ eWhh1,
    const float* __restrict__ dWih0, const float* __restrict__ dWhh0,
    const float* __restrict__ dWih1, const float* __restrict__ dWhh1,
    const float* __restrict__ outW,  const float* __restrict__ emb,
    const int*   __restrict__ src)
{
    if (blockIdx.x == 0 && threadIdx.x == 0) g_bar_count = 0u;
    int i = blockIdx.x;
    if (i < 2048)  { do_tr(eWih0, g_WTe0, E, R4H, 0, i & 15, i >> 4); return; }
    i -= 2048;
    if (i < 4096)  { do_tr(eWhh0, g_WTe0, H, R4H, E, i & 31, i >> 5); return; }
    i -= 4096;
    if (i < 4096)  { do_tr(eWih1, g_WTe1, H, R4H, 0, i & 31, i >> 5); return; }
    i -= 4096;
    if (i < 4096)  { do_tr(eWhh1, g_WTe1, H, R4H, H, i & 31, i >> 5); return; }
    i -= 4096;
    if (i < 2048)  { do_tr(dWih0, g_WTd0, E, R4H, 0, i & 15, i >> 4); return; }
    i -= 2048;
    if (i < 4096)  { do_tr(dWhh0, g_WTd0, H, R4H, E, i & 31, i >> 5); return; }
    i -= 4096;
    if (i < 4096)  { do_tr(dWih1, g_WTd1, H, R4H, 0, i & 31, i >> 5); return; }
    i -= 4096;
    if (i < 4096)  { do_tr(dWhh1, g_WTd1, H, R4H, H, i & 31, i >> 5); return; }
    i -= 4096;
    if (i < 32000) { do_tr(outW,  g_outWT, H, V,  0, i & 31, i >> 5); return; }
    i -= 32000;
    do_gather(emb, src, i & 3, i >> 2);
}

// ---------------- gates: cp.async weights, 32 rows x 16 batches (R14, unchanged) ----
__device__ __forceinline__ void fill_w(uint32_t s_w_u32, int buf,
                                       const float* __restrict__ wsrc)
{
    const int tid = threadIdx.x;
    #pragma unroll
    for (int r = 0; r < 2; r++) {
        int seg = tid + r * 256;          // 512 segs of 16B = 16 k-rows x 512B
        int kk = seg >> 5, sof = seg & 31;
        const float* src = wsrc + (size_t)kk * R4H + sof * 4;
        CP_ASYNC16(s_w_u32 + buf * 8192 + seg * 16, src);
    }
    CP_COMMIT();
}

__device__ void gates_phase(int taskbase, int nslice, int KS,
                            const float* __restrict__ xT, int KX,
                            const float* __restrict__ hT,
                            const float* __restrict__ WT,
                            float* __restrict__ part,
                            float* __restrict__ s_x,
                            float* __restrict__ s_w)
{
    const int tid = threadIdx.x;
    const int gw = blockIdx.x * 8 + (tid >> 5);
    const int task = gw - taskbase;
    if (task < 0 || task >= nslice * 256) return;   // CTA-uniform
    const int lane = tid & 31;
    const int s = task >> 8;
    const int pos = task & 255;
    const int bh = pos & 1, rg = pos >> 1;
    const int myrow = rg * 32 + (lane >> 2) * 4;
    const int bcol  = bh * 16 + (lane & 3) * 4;
    const int klo = s * KS;
    const int rowBase = (pos >> 3) * 128;           // same for all 8 warps
    const int wlr = myrow - rowBase;                // 0..124
    const uint32_t s_w_u32 = (uint32_t)__cvta_generic_to_shared(s_w);

    // stage activations for this slice (ordered by first __syncthreads below)
    const int nf4 = KS * 8;
    for (int i = tid; i < nf4; i += 256) {
        int gk = klo + (i >> 3);
        int off = i & 7;
        const float4* src4 = (gk < KX)
            ? (const float4*)(xT + (size_t)gk * B)
            : (const float4*)(hT + (size_t)(gk - KX) * B);
        ((float4*)s_x)[i] = src4[off];
    }

    unsigned long long acc[2][4];
    #pragma unroll
    for (int a = 0; a < 2; a++)
        #pragma unroll
        for (int b = 0; b < 4; b++) acc[a][b] = 0ull;

    const float* wsrc0 = WT + (size_t)klo * R4H + rowBase;
    const int nch = KS >> 4;                        // 16-k chunks
    fill_w(s_w_u32, 0, wsrc0);
    int buf = 0;

    for (int cc = 0; cc < nch; cc++) {
        if (cc + 1 < nch) {
            fill_w(s_w_u32, buf ^ 1, wsrc0 + (size_t)(cc + 1) * 16 * R4H);
            CP_WAIT1();
        } else {
            CP_WAIT0();
        }
        __syncthreads();                            // chunk cc visible (and x on cc=0)

        const float* ws = s_w + (buf << 11) + wlr;  // buf*2048 floats
        const float* xs = s_x + cc * 512 + bcol;    // cc*16*32 floats
        #pragma unroll
        for (int kk = 0; kk < 16; kk++) {
            ulonglong2 w2 = *(const ulonglong2*)(ws + kk * 128);
            float4 x4 = *(const float4*)(xs + kk * 32);
            unsigned long long xx;
            PACKXX(xx, x4.x); FMA2(acc[0][0], w2.x, xx); FMA2(acc[1][0], w2.y, xx);
            PACKXX(xx, x4.y); FMA2(acc[0][1], w2.x, xx); FMA2(acc[1][1], w2.y, xx);
            PACKXX(xx, x4.z); FMA2(acc[0][2], w2.x, xx); FMA2(acc[1][2], w2.y, xx);
            PACKXX(xx, x4.w); FMA2(acc[0][3], w2.x, xx); FMA2(acc[1][3], w2.y, xx);
        }
        __syncthreads();                            // all reads done before refill
        buf ^= 1;
    }

    float vr[4][4];
    #pragma unroll
    for (int b = 0; b < 4; b++) {
        UNPACK2(vr[0][b], vr[1][b], acc[0][b]);
        UNPACK2(vr[2][b], vr[3][b], acc[1][b]);
    }
    float* p = part + (size_t)s * R4H * B;
    #pragma unroll
    for (int r = 0; r < 4; r++)
        *(float4*)(p + (size_t)(myrow + r) * B + bcol) =
            make_float4(vr[r][0], vr[r][1], vr[r][2], vr[r][3]);
}

// ---------------- cell: combine partials + bias + LSTM cell ----------------
__device__ void cell_phase(int blockbase, int nslice,
                           const float* __restrict__ part,
                           const float* __restrict__ bias,
                           float* __restrict__ cT, float* __restrict__ hOut)
{
    const int cb = blockIdx.x - blockbase;
    if (cb < 0 || cb >= 128) return;
    const int idx = cb * 256 + threadIdx.x;
    const int j = idx >> 5, b = idx & 31;
    float g[4];
    #pragma unroll
    for (int gg = 0; gg < 4; gg++) g[gg] = bias[gg * H + j];
    #pragma unroll 4
    for (int s = 0; s < nslice; s++) {
        const float* p = part + (size_t)s * R4H * B + b;
        #pragma unroll
        for (int gg = 0; gg < 4; gg++)
            g[gg] += p[(size_t)(gg * H + j) * B];
    }
    float c_old = cT[j * B + b];
    float c_new = sigm(g[1]) * c_old + sigm(g[0]) * tanhf(g[2]);
    cT[j * B + b]   = c_new;
    hOut[j * B + b] = sigm(g[3]) * tanhf(c_new);
}

// ---------------- logits: cp.async weight chunks + staged x + fused argmax ----------
// CTA c owns 64 vocab rows. 32 pair-chunks of 16 k (both ks halves), double-buffered
// in s_aux (2 x 8 KB). x staged per 128-k block (every 8th chunk) into s_x.
__device__ __forceinline__ void fill_lw(uint32_t s_w_u32, int buf, int cc, int c)
{
    const int tid = threadIdx.x;
    #pragma unroll
    for (int r = 0; r < 2; r++) {
        int seg = tid + r * 256;              // 512 segs: half = seg>>8
        int half = seg >> 8, s2 = seg & 255;
        int k = s2 >> 4, off = s2 & 15;       // 16 k-rows x 16 segs (64 rows x 4B)
        const float* src = g_outWT + (size_t)(half * 512 + cc * 16 + k) * V
                         + c * 64 + off * 4;
        CP_ASYNC16(s_w_u32 + buf * 8192 + half * 4096 + k * 256 + off * 16, src);
    }
    CP_COMMIT();
}

__device__ void logits_phase(const float* __restrict__ h1T,
                             const float* __restrict__ outB,
                             float* __restrict__ out, int step,
                             float* __restrict__ s_x,
                             unsigned long long* __restrict__ s_aux)
{
    const int c = blockIdx.x;
    if (c >= LCTAS) return;
    const int tid = threadIdx.x;
    const int w = tid >> 5, lane = tid & 31;
    const int ks = w & 1, bh = (w >> 1) & 1, rgh = w >> 2;
    const int rowl = rgh * 32 + (lane >> 2) * 4;          // 0..60 CTA-local row
    const int vrow = c * 64 + rowl;
    const int bcol = bh * 16 + (lane & 3) * 4;
    const uint32_t s_w_u32 = (uint32_t)__cvta_generic_to_shared((float*)s_aux);
    float* s_wf = (float*)s_aux;

    unsigned long long acc[2][4];
    #pragma unroll
    for (int a = 0; a < 2; a++)
        #pragma unroll
        for (int b = 0; b < 4; b++) acc[a][b] = 0ull;

    fill_lw(s_w_u32, 0, 0, c);
    int buf = 0;

    for (int cc = 0; cc < 32; cc++) {
        if (cc + 1 < 32) fill_lw(s_w_u32, buf ^ 1, cc + 1, c);
        if ((cc & 7) == 0) {
            // stage x for 128-k block ci = cc>>3 (both halves)
            int ci = cc >> 3;
            const float4* sA = (const float4*)(h1T + (size_t)(ci * 128) * B);
            const float4* sB = (const float4*)(h1T + (size_t)(512 + ci * 128) * B);
            float4* dA = (float4*)s_x;
            float4* dB = (float4*)(s_x + 4096);
            #pragma unroll
            for (int i = 0; i < 4; i++) {
                dA[tid + i * 256] = sA[tid + i * 256];
                dB[tid + i * 256] = sB[tid + i * 256];
            }
        }
        if (cc + 1 < 32) { CP_WAIT1(); } else { CP_WAIT0(); }
        __syncthreads();                    // w(cc) + x(ci) visible

        const float* ws = s_wf + (buf << 11) + (ks << 10) + rowl;
        const float* xs = s_x + ks * 4096 + (cc & 7) * 512 + bcol;
        #pragma unroll
        for (int kk = 0; kk < 16; kk++) {
            ulonglong2 w2 = *(const ulonglong2*)(ws + kk * 64);
            float4 x4 = *(const float4*)(xs + kk * 32);
            unsigned long long xx;
            PACKXX(xx, x4.x); FMA2(acc[0][0], w2.x, xx); FMA2(acc[1][0], w2.y, xx);
            PACKXX(xx, x4.y); FMA2(acc[0][1], w2.x, xx); FMA2(acc[1][1], w2.y, xx);
            PACKXX(xx, x4.z); FMA2(acc[0][2], w2.x, xx); FMA2(acc[1][2], w2.y, xx);
            PACKXX(xx, x4.w); FMA2(acc[0][3], w2.x, xx); FMA2(acc[1][3], w2.y, xx);
        }
        __syncthreads();                    // reads done before refill
        buf ^= 1;
    }

    // s_aux reusable now: combine (8 KB) + argmax scratch
    unsigned long long (*s_comb)[32][8] = (unsigned long long (*)[32][8])s_aux;
    float* s_av = (float*)(s_aux + 1024);
    int*   s_ai = (int*)((float*)(s_aux + 1024) + 64);

    if (ks) {
        #pragma unroll
        for (int a = 0; a < 8; a++) s_comb[w >> 1][lane][a] = acc[a >> 2][a & 3];
    }
    __syncthreads();
    if (!ks) {
        #pragma unroll
        for (int a = 0; a < 8; a++) {
            unsigned long long o = s_comb[w >> 1][lane][a];
            ADD2(acc[a >> 2][a & 3], acc[a >> 2][a & 3], o);
        }
        float4 b4 = *(const float4*)(outB + vrow);
        float vr[4][4];
        #pragma unroll
        for (int b = 0; b < 4; b++) {
            UNPACK2(vr[0][b], vr[1][b], acc[0][b]);
            UNPACK2(vr[2][b], vr[3][b], acc[1][b]);
            vr[0][b] += b4.x; vr[1][b] += b4.y; vr[2][b] += b4.z; vr[3][b] += b4.w;
        }
        float mval[4]; int midx[4];
        #pragma unroll
        for (int b = 0; b < 4; b++) {
            *(float4*)(out + (size_t)(bcol + b) * (L * V) + (size_t)step * V + vrow) =
                make_float4(vr[0][b], vr[1][b], vr[2][b], vr[3][b]);
            float bv = vr[0][b]; int bi = vrow;
            #pragma unroll
            for (int r = 1; r < 4; r++)
                if (vr[r][b] > bv) { bv = vr[r][b]; bi = vrow + r; }
            mval[b] = bv; midx[b] = bi;
        }
        #pragma unroll
        for (int off = 16; off >= 4; off >>= 1) {
            #pragma unroll
            for (int b = 0; b < 4; b++) {
                float ov = __shfl_down_sync(0xffffffffu, mval[b], off);
                int   oi = __shfl_down_sync(0xffffffffu, midx[b], off);
                if (ov > mval[b] || (ov == mval[b] && oi < midx[b])) {
                    mval[b] = ov; midx[b] = oi;
                }
            }
        }
        if (lane < 4) {
            #pragma unroll
            for (int b = 0; b < 4; b++) {
                s_av[rgh * 32 + bh * 16 + lane * 4 + b] = mval[b];
                s_ai[rgh * 32 + bh * 16 + lane * 4 + b] = midx[b];
            }
        }
    }
    __syncthreads();
    if (tid < 32) {
        float v0 = s_av[tid], v1 = s_av[32 + tid];
        int   i0 = s_ai[tid], i1 = s_ai[32 + tid];
        bool take1 = (v1 > v0) || (v1 == v0 && i1 < i0);
        g_pval[c * B + tid] = take1 ? v1 : v0;
        g_pidx[c * B + tid] = take1 ? i1 : i0;
    }
}

// ---------------- argmax final + next-token embedding gather ----------------
__device__ void argmax_gather_phase(const float* __restrict__ emb, bool do_argmax,
                                    unsigned long long* __restrict__ s_aux)
{
    float* sval = (float*)s_aux;             // 256 floats
    int*   sidx = (int*)(s_aux + 128);       // 256 ints
    const int c = blockIdx.x;
    if (c >= B) return;
    const int b = c, tid = threadIdx.x;
    int tk;
    if (do_argmax) {
        float bv = -INFINITY; int bi = 0x7fffffff;
        for (int i2 = tid; i2 < LCTAS; i2 += 256) {
            float v = g_pval[i2 * B + b]; int i = g_pidx[i2 * B + b];
            if (v > bv || (v == bv && i < bi)) { bv = v; bi = i; }
        }
        sval[tid] = bv; sidx[tid] = bi;
        __syncthreads();
        for (int off = 128; off; off >>= 1) {
            if (tid < off) {
                float v = sval[tid + off]; int i = sidx[tid + off];
                if (v > sval[tid] || (v == sval[tid] && i < sidx[tid])) {
                    sval[tid] = v; sidx[tid] = i;
                }
            }
            __syncthreads();
        }
        tk = sidx[0];
    } else {
        tk = BOS;
    }
    for (int k = tid; k < E; k += 256)
        g_xdT[k * B + b] = emb[(size_t)tk * E + k];
}

// ---------------- persistent model kernel ----------------
__global__ __launch_bounds__(256, 4) void model_kernel(
    const float* __restrict__ emb,
    const float* __restrict__ eb0, const float* __restrict__ eb1,
    const float* __restrict__ db0, const float* __restrict__ db1,
    const float* __restrict__ outB,
    float* __restrict__ out)
{
    __shared__ float s_x[8192];                 // 32 KB: x staging
    __shared__ unsigned long long s_aux[2048];  // 16 KB: w dbl-buf / comb / argmax

    const int tid = threadIdx.x;
    unsigned bt = 0;

    for (int i = blockIdx.x * 256 + tid; i < H * B; i += NB * 256) {
        g_h0T[0][i] = 0.f; g_h1T[0][i] = 0.f;
        g_c0T[i] = 0.f;    g_c1T[i] = 0.f;
    }
    grid_barrier(bt += NB);

    int p0 = 0, p1 = 0;
    float* s_w = (float*)s_aux;

    // ---- encoder, software-pipelined (L1(t) || L0(t+1)) ----
    gates_phase(0, 6, 256, g_xsT, E, g_h0T[p0], g_WTe0, g_part0, s_x, s_w); // L0 t=0
    grid_barrier(bt += NB);
    cell_phase(0, 6, g_part0, eb0, g_c0T, g_h0T[p0 ^ 1]);
    p0 ^= 1;
    grid_barrier(bt += NB);

    for (int t = 0; t < T; t++) {
        gates_phase(0, 8, 256, g_h0T[p0], H, g_h1T[p1], g_WTe1, g_part1,
                    s_x, s_w);                                              // L1(t)
        if (t + 1 < T)
            gates_phase(2048, 6, 256, g_xsT + (size_t)(t + 1) * E * B, E,
                        g_h0T[p0], g_WTe0, g_part0, s_x, s_w);              // L0(t+1)
        grid_barrier(bt += NB);
        cell_phase(0, 8, g_part1, eb1, g_c1T, g_h1T[p1 ^ 1]);
        p1 ^= 1;
        if (t + 1 < T) {
            cell_phase(128, 6, g_part0, eb0, g_c0T, g_h0T[p0 ^ 1]);
            p0 ^= 1;
        }
        grid_barrier(bt += NB);
    }

    // ---- BOS gather ----
    argmax_gather_phase(emb, false, s_aux);
    grid_barrier(bt += NB);

    // ---- greedy decoder ----
    for (int s = 0; s < L; s++) {
        gates_phase(0, 16, 96, g_xdT, E, g_h0T[p0], g_WTd0, g_part0, s_x, s_w);
        grid_barrier(bt += NB);
        cell_phase(0, 16, g_part0, db0, g_c0T, g_h0T[p0 ^ 1]);
        p0 ^= 1;
        grid_barrier(bt += NB);
        gates_phase(0, 16, 128, g_h0T[p0], H, g_h1T[p1], g_WTd1, g_part1, s_x, s_w);
        grid_barrier(bt += NB);
        cell_phase(0, 16, g_part1, db1, g_c1T, g_h1T[p1 ^ 1]);
        p1 ^= 1;
        grid_barrier(bt += NB);
        logits_phase(g_h1T[p1], outB, out, s, s_x, s_aux);
        grid_barrier(bt += NB);
        argmax_gather_phase(emb, true, s_aux);
        grid_barrier(bt += NB);
    }
}

// ---------------- host orchestration: 2 launches per call ----------------
extern "C" void kernel_launch(void* const* d_in, const int* in_sizes, int n_in,
                              void* d_out, int out_size)
{
    const int*   src   = (const int*)  d_in[0];
    const float* emb   = (const float*)d_in[1];
    const float* eWih0 = (const float*)d_in[2];
    const float* eWhh0 = (const float*)d_in[3];
    const float* eb0   = (const float*)d_in[4];
    const float* eWih1 = (const float*)d_in[5];
    const float* eWhh1 = (const float*)d_in[6];
    const float* eb1   = (const float*)d_in[7];
    const float* dWih0 = (const float*)d_in[8];
    const float* dWhh0 = (const float*)d_in[9];
    const float* db0   = (const float*)d_in[10];
    const float* dWih1 = (const float*)d_in[11];
    const float* dWhh1 = (const float*)d_in[12];
    const float* db1   = (const float*)d_in[13];
    const float* outW  = (const float*)d_in[14];
    const float* outB  = (const float*)d_in[15];
    float* out = (float*)d_out;

    prep_kernel<<<PREP_BLOCKS, 256>>>(eWih0, eWhh0, eWih1, eWhh1,
                                      dWih0, dWhh0, dWih1, dWhh1,
                                      outW, emb, src);

    model_kernel<<<NB, 256>>>(emb, eb0, eb1, db0, db1, outB, out);
}